// round 1
// baseline (speedup 1.0000x reference)
#include <cuda_runtime.h>

#define NQ 12
#define SIZE 4096           // 2^12 amplitudes
#define THREADS 256
#define PI_F 3.14159265358979323846f

// Precomputed (batch-independent) circuit data
__device__ float2   d_U0[NQ][2][2];     // layer-0 Rot matrices (folded into init)
__device__ float2   d_gm[5][6][16];     // layers 1..5: fused 4x4 gates per qubit pair (2p,2p+1)
__device__ unsigned d_rmask[6][NQ];     // per-layer CNOT-ring read-index masks (GF(2) basis images)

__device__ __forceinline__ float2 cmul(float2 a, float2 b) {
    return make_float2(a.x * b.x - a.y * b.y, a.x * b.y + a.y * b.x);
}
__device__ __forceinline__ void cmad(float2& y, float2 m, float2 x) {
    y.x = fmaf(m.x, x.x, y.x);
    y.x = fmaf(-m.y, x.y, y.x);
    y.y = fmaf(m.x, x.y, y.y);
    y.y = fmaf(m.y, x.x, y.y);
}

// ---------------------------------------------------------------------------
// Precompute kernel: Rot matrices, fused 4x4 pair gates, CNOT-layer masks
// ---------------------------------------------------------------------------
__global__ void precompute_kernel(const float* __restrict__ weights) {
    __shared__ float2 U[6][NQ][2][2];
    int tid = threadIdx.x;

    // Rot(phi, theta, omega) per PennyLane convention
    for (int g = tid; g < 6 * NQ; g += blockDim.x) {
        float phi = weights[g * 3 + 0];
        float th  = weights[g * 3 + 1];
        float om  = weights[g * 3 + 2];
        float c, s;
        __sincosf(0.5f * th, &s, &c);
        s = sinf(0.5f * th); c = cosf(0.5f * th);   // full-precision
        float ap = 0.5f * (phi + om), am = 0.5f * (phi - om);
        float sap = sinf(ap), cap = cosf(ap);
        float sam = sinf(am), cam = cosf(am);
        int l = g / NQ, w = g % NQ;
        U[l][w][0][0] = make_float2(cap * c, -sap * c);   //  e^{-i(phi+om)/2} cos
        U[l][w][0][1] = make_float2(-cam * s, -sam * s);  // -e^{+i(phi-om)/2} sin
        U[l][w][1][0] = make_float2(cam * s, -sam * s);   //  e^{-i(phi-om)/2} sin
        U[l][w][1][1] = make_float2(cap * c, sap * c);    //  e^{+i(phi+om)/2} cos
    }
    __syncthreads();

    // layer-0 matrices raw (folded into per-batch init)
    for (int e = tid; e < NQ * 4; e += blockDim.x) {
        int w = e >> 2, j = (e >> 1) & 1, k = e & 1;
        d_U0[w][j][k] = U[0][w][j][k];
    }
    // fused 4x4 = kron(U[b], U[a]) for pair a=2p (low bit), b=2p+1 (high bit), layers 1..5
    for (int e = tid; e < 5 * 6 * 16; e += blockDim.x) {
        int l = e / 96 + 1, rem = e % 96, p = rem >> 4, jk = rem & 15;
        int j = jk >> 2, k = jk & 3;
        float2 ua = U[l][2 * p][j & 1][k & 1];
        float2 ub = U[l][2 * p + 1][(j >> 1) & 1][(k >> 1) & 1];
        d_gm[l - 1][p][jk] = cmul(ua, ub);
    }
    // CNOT-ring read map R for each layer: s_after[j] = s_before[R(j)];
    // R = f_{w=0} ∘ ... ∘ f_{w=11} with f(j) = j ^ (bit_c(j) << t), applied w=11..0.
    // R is GF(2)-linear: store the 12 basis images.
    for (int e = tid; e < 6 * NQ; e += blockDim.x) {
        int l = e / NQ, bb = e % NQ;
        int r = (l % (NQ - 1)) + 1;
        unsigned i = 1u << bb;
        for (int w = NQ - 1; w >= 0; --w) {
            int c = w, tg = (w + r) % NQ;
            i ^= ((i >> c) & 1u) << tg;
        }
        d_rmask[l][bb] = i;
    }
}

// ---------------------------------------------------------------------------
// Gate passes
// ---------------------------------------------------------------------------

// Fused 4x4 gate on qubits (A, A+1) where both bits live in lane-space (A in {0,2}).
// Each lane owns amp at logical index i = t + 256*m; partners gathered via shfl_xor.
// Optional MASKED: reads go through the previous layer's CNOT permutation R.
template <int A, bool MASKED>
__device__ __forceinline__ void pass_shfl(const float2* __restrict__ in,
                                          float2* __restrict__ out,
                                          const float2* gm, const unsigned* rm, int t) {
    int lane = t & 31;
    int j = (lane >> A) & 3;
    // coefficients for my output row, ordered by shuffle distance d: M[j][j^d]
    float2 md0 = gm[j * 4 + j];
    float2 md1 = gm[j * 4 + (j ^ 1)];
    float2 md2 = gm[j * 4 + (j ^ 2)];
    float2 md3 = gm[j * 4 + (j ^ 3)];

    unsigned rt = 0, rm8 = 0, rm9 = 0, rm10 = 0, rm11 = 0;
    if (MASKED) {
#pragma unroll
        for (int bb = 0; bb < 8; bb++)
            rt ^= rm[bb] & (unsigned)(-(int)((t >> bb) & 1));
        rm8 = rm[8]; rm9 = rm[9]; rm10 = rm[10]; rm11 = rm[11];
    }
#pragma unroll
    for (int m = 0; m < 16; m++) {
        int i = t + 256 * m;
        unsigned addr = (unsigned)i;
        if (MASKED) {
            addr = rt;
            if (m & 1) addr ^= rm8;
            if (m & 2) addr ^= rm9;
            if (m & 4) addr ^= rm10;
            if (m & 8) addr ^= rm11;
        }
        float2 x0 = in[addr];
        float2 x1, x2, x3;
        x1.x = __shfl_xor_sync(0xFFFFFFFFu, x0.x, 1 << A);
        x1.y = __shfl_xor_sync(0xFFFFFFFFu, x0.y, 1 << A);
        x2.x = __shfl_xor_sync(0xFFFFFFFFu, x0.x, 2 << A);
        x2.y = __shfl_xor_sync(0xFFFFFFFFu, x0.y, 2 << A);
        x3.x = __shfl_xor_sync(0xFFFFFFFFu, x0.x, 3 << A);
        x3.y = __shfl_xor_sync(0xFFFFFFFFu, x0.y, 3 << A);
        float2 y = make_float2(0.f, 0.f);
        cmad(y, md0, x0);
        cmad(y, md1, x1);
        cmad(y, md2, x2);
        cmad(y, md3, x3);
        out[i] = y;
    }
}

// Fused 4x4 gate on qubits (A, A+1), A >= 4: direct SMEM gather.
// Group id g covers the 10 non-gate bits; lanes map to the lowest 5 -> conflict-free LDS.64.
template <int A>
__device__ __forceinline__ void pass_smem(const float2* __restrict__ in,
                                          float2* __restrict__ out,
                                          const float2* gm, int t) {
    float2 M[16];
#pragma unroll
    for (int e = 0; e < 16; e++) M[e] = gm[e];
    const int SA = 1 << A;
#pragma unroll
    for (int mm = 0; mm < 4; mm++) {
        int g = t + 256 * mm;
        int base = ((g >> A) << (A + 2)) | (g & (SA - 1));
        float2 x0 = in[base];
        float2 x1 = in[base + SA];
        float2 x2 = in[base + 2 * SA];
        float2 x3 = in[base + 3 * SA];
        float2 y0 = make_float2(0.f, 0.f), y1 = y0, y2 = y0, y3 = y0;
        cmad(y0, M[0], x0);  cmad(y0, M[1], x1);  cmad(y0, M[2], x2);  cmad(y0, M[3], x3);
        cmad(y1, M[4], x0);  cmad(y1, M[5], x1);  cmad(y1, M[6], x2);  cmad(y1, M[7], x3);
        cmad(y2, M[8], x0);  cmad(y2, M[9], x1);  cmad(y2, M[10], x2); cmad(y2, M[11], x3);
        cmad(y3, M[12], x0); cmad(y3, M[13], x1); cmad(y3, M[14], x2); cmad(y3, M[15], x3);
        out[base] = y0;
        out[base + SA] = y1;
        out[base + 2 * SA] = y2;
        out[base + 3 * SA] = y3;
    }
}

// ---------------------------------------------------------------------------
// Main kernel: one CTA per batch element
// ---------------------------------------------------------------------------
extern __shared__ float2 smem[];

__global__ void __launch_bounds__(THREADS) qvl_kernel(
    const float* __restrict__ v, const float* __restrict__ W,
    const float* __restrict__ bc, float* __restrict__ out) {
    float2*   S0  = smem;                 // 4096
    float2*   S1  = smem + SIZE;          // 4096
    float2*   sA  = smem + 2 * SIZE;      // 24: per-qubit 2-vectors after RY+layer0 Rot
    float2*   sH  = sA + 24;              // 16: product over bits 8..11
    float2*   sGM = sH + 16;              // 480: fused gates layers 1..5
    unsigned* sRM = (unsigned*)(sGM + 480); // 72: CNOT masks

    int b = blockIdx.x;
    int t = threadIdx.x;
    int lane = t & 31, warp = t >> 5;

    // Stage gate data into SMEM
    {
        const float2* g0 = &d_gm[0][0][0];
        for (int e = t; e < 480; e += THREADS) sGM[e] = g0[e];
        const unsigned* r0 = &d_rmask[0][0];
        if (t < 72) sRM[t] = r0[t];
    }

    // Angles: x_w = tanh(v[b]·W[w] + b[w]) * pi ; then fold layer-0 Rot:
    // a_w = U0_w @ (cos(x/2), sin(x/2))
    const float* vrow = v + (size_t)b * 512;
    for (int w = warp; w < NQ; w += 8) {
        const float* Wr = W + w * 512;
        float acc = 0.f;
#pragma unroll
        for (int q = 0; q < 16; q++)
            acc = fmaf(vrow[lane + 32 * q], Wr[lane + 32 * q], acc);
#pragma unroll
        for (int o = 16; o; o >>= 1) acc += __shfl_xor_sync(0xFFFFFFFFu, acc, o);
        if (lane == 0) {
            float x = tanhf(acc + bc[w]) * PI_F;
            float ch = cosf(0.5f * x), sh = sinf(0.5f * x);
            float2 u00 = d_U0[w][0][0], u01 = d_U0[w][0][1];
            float2 u10 = d_U0[w][1][0], u11 = d_U0[w][1][1];
            sA[2 * w + 0] = make_float2(u00.x * ch + u01.x * sh, u00.y * ch + u01.y * sh);
            sA[2 * w + 1] = make_float2(u10.x * ch + u11.x * sh, u10.y * ch + u11.y * sh);
        }
    }
    __syncthreads();
    if (t < 16) {
        float2 h = sA[16 + (t & 1)];
        h = cmul(h, sA[18 + ((t >> 1) & 1)]);
        h = cmul(h, sA[20 + ((t >> 2) & 1)]);
        h = cmul(h, sA[22 + ((t >> 3) & 1)]);
        sH[t] = h;
    }
    __syncthreads();

    // Product-state init (RY embedding + layer-0 Rot already folded into sA)
    {
        float2 tp = sA[(t & 1)];
#pragma unroll
        for (int w = 1; w < 8; w++)
            tp = cmul(tp, sA[2 * w + ((t >> w) & 1)]);
#pragma unroll
        for (int m = 0; m < 16; m++)
            S0[t + 256 * m] = cmul(tp, sH[m]);
    }
    __syncthreads();

    float2* cur = S0;
    float2* nxt = S1;
#pragma unroll 1
    for (int l = 1; l <= 5; l++) {
        const float2* gm = sGM + (l - 1) * 96;
        const unsigned* rm = sRM + (l - 1) * 12;  // CNOT ring of layer l-1 folded into first pass
        pass_shfl<0, true>(cur, nxt, gm, rm, t);
        { float2* tmp = cur; cur = nxt; nxt = tmp; }
        __syncthreads();
        pass_shfl<2, false>(cur, nxt, gm + 16, (const unsigned*)0, t);
        { float2* tmp = cur; cur = nxt; nxt = tmp; }
        __syncthreads();
        pass_smem<4>(cur, nxt, gm + 32, t);
        { float2* tmp = cur; cur = nxt; nxt = tmp; }
        __syncthreads();
        pass_smem<6>(cur, nxt, gm + 48, t);
        { float2* tmp = cur; cur = nxt; nxt = tmp; }
        __syncthreads();
        pass_smem<8>(cur, nxt, gm + 64, t);
        { float2* tmp = cur; cur = nxt; nxt = tmp; }
        __syncthreads();
        pass_smem<10>(cur, nxt, gm + 80, t);
        { float2* tmp = cur; cur = nxt; nxt = tmp; }
        __syncthreads();
    }

    // Expvals: read through the final CNOT layer's mask; Walsh-style signed reduction.
    {
        const unsigned* rm = sRM + 5 * 12;
        unsigned rt = 0;
#pragma unroll
        for (int bb = 0; bb < 8; bb++)
            rt ^= rm[bb] & (unsigned)(-(int)((t >> bb) & 1));
        unsigned rm8 = rm[8], rm9 = rm[9], rm10 = rm[10], rm11 = rm[11];
        float P = 0.f, Z8 = 0.f, Z9 = 0.f, Z10 = 0.f, Z11 = 0.f;
#pragma unroll
        for (int m = 0; m < 16; m++) {
            unsigned addr = rt;
            if (m & 1) addr ^= rm8;
            if (m & 2) addr ^= rm9;
            if (m & 4) addr ^= rm10;
            if (m & 8) addr ^= rm11;
            float2 x = cur[addr];
            float p = fmaf(x.x, x.x, x.y * x.y);
            P += p;
            Z8  += (m & 1) ? -p : p;
            Z9  += (m & 2) ? -p : p;
            Z10 += (m & 4) ? -p : p;
            Z11 += (m & 8) ? -p : p;
        }
        float* red = (float*)nxt;   // scratch: the buffer NOT holding the state
        red[t] = P;
        red[256 + t] = Z8;
        red[512 + t] = Z9;
        red[768 + t] = Z10;
        red[1024 + t] = Z11;
        __syncthreads();
        for (int w = warp; w < NQ; w += 8) {
            const float* src = (w < 8) ? red : red + 256 * (w - 7);
            float s = 0.f;
#pragma unroll
            for (int q = 0; q < 8; q++) {
                int tt = lane + 32 * q;
                float val = src[tt];
                if (w < 8 && ((tt >> w) & 1)) val = -val;
                s += val;
            }
#pragma unroll
            for (int o = 16; o; o >>= 1) s += __shfl_xor_sync(0xFFFFFFFFu, s, o);
            if (lane == 0) out[b * NQ + w] = s;
        }
    }
}

// ---------------------------------------------------------------------------
extern "C" void kernel_launch(void* const* d_in, const int* in_sizes, int n_in,
                              void* d_out, int out_size) {
    // Identify inputs by element count (all distinct): v=2097152, W=6144, b=12, weights=216
    const float* v = 0; const float* W = 0; const float* bc = 0; const float* wt = 0;
    for (int i = 0; i < n_in; i++) {
        if (in_sizes[i] == 4096 * 512) v  = (const float*)d_in[i];
        else if (in_sizes[i] == 12 * 512) W = (const float*)d_in[i];
        else if (in_sizes[i] == 12)       bc = (const float*)d_in[i];
        else if (in_sizes[i] == 6 * 12 * 3) wt = (const float*)d_in[i];
    }
    float* out = (float*)d_out;

    precompute_kernel<<<1, 128>>>(wt);

    size_t shmem = (size_t)(2 * SIZE + 24 + 16 + 480) * sizeof(float2) + 72 * sizeof(unsigned);
    cudaFuncSetAttribute(qvl_kernel, cudaFuncAttributeMaxDynamicSharedMemorySize, (int)shmem);
    qvl_kernel<<<4096, THREADS, shmem>>>(v, W, bc, out);
}

// round 2
// speedup vs baseline: 1.2282x; 1.2282x over previous
#include <cuda_runtime.h>

#define NQ 12
#define SIZE 4096
#define THREADS 256
#define PI_F 3.14159265358979323846f
typedef unsigned long long u64;

// Precomputed (batch-independent) circuit data
__device__ float2   d_U0[NQ][2][2];   // layer-0 Rot (folded into init)
__device__ u64      d_G[5 * 12 * 8];  // layers 1..5, per qubit: 4 coeffs x (c1=(re,re), c2=(-im,im))
__device__ unsigned d_rmask[6 * NQ];  // [0..4]: forward CNOT masks; [5]: INVERSE masks of layer-5 ring

__device__ __forceinline__ float2 cmul(float2 a, float2 b) {
    return make_float2(a.x * b.x - a.y * b.y, a.x * b.y + a.y * b.x);
}
__device__ __forceinline__ u64 pk2(float a, float b) {
    u64 r; asm("mov.b64 %0,{%1,%2};" : "=l"(r) : "f"(a), "f"(b)); return r;
}
__device__ __forceinline__ u64 f2u(float2 v) {
    u64 r; asm("mov.b64 %0,{%1,%2};" : "=l"(r) : "f"(v.x), "f"(v.y)); return r;
}
__device__ __forceinline__ float2 u2f(u64 v) {
    float2 r; asm("mov.b64 {%0,%1},%2;" : "=f"(r.x), "=f"(r.y) : "l"(v)); return r;
}

// ---------------------------------------------------------------------------
// Precompute kernel
// ---------------------------------------------------------------------------
__global__ void precompute_kernel(const float* __restrict__ weights) {
    __shared__ float2 U[6][NQ][2][2];
    int tid = threadIdx.x;

    for (int g = tid; g < 6 * NQ; g += blockDim.x) {
        float phi = weights[g * 3 + 0];
        float th  = weights[g * 3 + 1];
        float om  = weights[g * 3 + 2];
        float s = sinf(0.5f * th), c = cosf(0.5f * th);
        float ap = 0.5f * (phi + om), am = 0.5f * (phi - om);
        float sap = sinf(ap), cap = cosf(ap);
        float sam = sinf(am), cam = cosf(am);
        int l = g / NQ, w = g % NQ;
        U[l][w][0][0] = make_float2(cap * c, -sap * c);
        U[l][w][0][1] = make_float2(-cam * s, -sam * s);
        U[l][w][1][0] = make_float2(cam * s, -sam * s);
        U[l][w][1][1] = make_float2(cap * c, sap * c);
    }
    __syncthreads();

    // layer-0 matrices raw (folded into per-batch init)
    for (int e = tid; e < NQ * 4; e += blockDim.x) {
        int w = e >> 2, j = (e >> 1) & 1, k = e & 1;
        d_U0[w][j][k] = U[0][w][j][k];
    }
    // packed-coefficient 2x2 gates, layers 1..5
    // layout per gate (8 u64): [c1(u00),c2(u00), c1(u01),c2(u01), c1(u10),c2(u10), c1(u11),c2(u11)]
    for (int e = tid; e < 5 * 12 * 4; e += blockDim.x) {
        int l = e / 48 + 1, rem = e % 48, q = rem >> 2, ik = rem & 3;
        float2 u = U[l][q][ik >> 1][ik & 1];
        int base = ((l - 1) * 12 + q) * 8 + ik * 2;
        d_G[base + 0] = pk2(u.x, u.x);
        d_G[base + 1] = pk2(-u.y, u.y);
    }
    // CNOT-ring masks. Forward for layers 0..4 (read-folding), inverse for layer 5 (expval fold).
    for (int e = tid; e < 6 * NQ; e += blockDim.x) {
        int l = e / NQ, bb = e % NQ;
        unsigned i = 1u << bb;
        if (l < 5) {
            int r = (l % (NQ - 1)) + 1;
            for (int w = NQ - 1; w >= 0; --w)
                i ^= ((i >> w) & 1u) << ((w + r) % NQ);
        } else {
            int r = (5 % (NQ - 1)) + 1;   // inverse: same involutions, reverse order
            for (int w = 0; w < NQ; ++w)
                i ^= ((i >> w) & 1u) << ((w + r) % NQ);
        }
        d_rmask[l * NQ + bb] = i;
    }
}

// ---------------------------------------------------------------------------
// Packed complex 2x2 application (register-resident)
// ---------------------------------------------------------------------------
__device__ __forceinline__ void app2(float2& a, float2& b, const u64* g) {
    u64 x0 = f2u(a), x1 = f2u(b);
    u64 x0s = f2u(make_float2(a.y, a.x));
    u64 x1s = f2u(make_float2(b.y, b.x));
    u64 y0, y1;
    asm("mul.rn.f32x2 %0,%1,%2;"    : "=l"(y0) : "l"(g[0]), "l"(x0));
    asm("fma.rn.f32x2 %0,%1,%2,%0;" : "+l"(y0) : "l"(g[1]), "l"(x0s));
    asm("fma.rn.f32x2 %0,%1,%2,%0;" : "+l"(y0) : "l"(g[2]), "l"(x1));
    asm("fma.rn.f32x2 %0,%1,%2,%0;" : "+l"(y0) : "l"(g[3]), "l"(x1s));
    asm("mul.rn.f32x2 %0,%1,%2;"    : "=l"(y1) : "l"(g[4]), "l"(x0));
    asm("fma.rn.f32x2 %0,%1,%2,%0;" : "+l"(y1) : "l"(g[5]), "l"(x0s));
    asm("fma.rn.f32x2 %0,%1,%2,%0;" : "+l"(y1) : "l"(g[6]), "l"(x1));
    asm("fma.rn.f32x2 %0,%1,%2,%0;" : "+l"(y1) : "l"(g[7]), "l"(x1s));
    a = u2f(y0); b = u2f(y1);
}

template <int Q>
__device__ __forceinline__ void gate_reg(float2* s, const u64* gg) {
    u64 g[8];
#pragma unroll
    for (int e = 0; e < 8; e++) g[e] = gg[e];
#pragma unroll
    for (int h = 0; h < 8; h++) {
        const int ST = 1 << Q;
        int m0 = ((h >> Q) << (Q + 1)) | (h & (ST - 1));
        app2(s[m0], s[m0 + ST], g);
    }
}

__device__ __forceinline__ void gates4(float2* s, const u64* gl) {
    gate_reg<0>(s, gl);
    gate_reg<1>(s, gl + 8);
    gate_reg<2>(s, gl + 16);
    gate_reg<3>(s, gl + 24);
}

// ---------------------------------------------------------------------------
// Main kernel: one CTA per batch element; full state in registers.
// SMEM state S holds amp j at swizzled address p(j) = j ^ ((j>>4)&15).
// Config A: j=(t<<4)|m ; Config B: j=(thi<<8)|(m<<4)|tlo ; Config C: j=(m<<8)|t
// ---------------------------------------------------------------------------
extern __shared__ unsigned char smem_raw[];

__global__ void __launch_bounds__(THREADS) qvl_kernel(
    const float* __restrict__ v, const float* __restrict__ W,
    const float* __restrict__ bc, float* __restrict__ out) {
    float2*   S   = (float2*)smem_raw;                       // 4096 amps (32768 B)
    u64*      sG  = (u64*)(smem_raw + 32768);                // 480 (3840 B)
    float2*   sA  = (float2*)(smem_raw + 32768 + 3840);      // 24
    float2*   sH  = sA + 24;                                 // 16
    unsigned* sRM = (unsigned*)(sA + 40);                    // 72

    int b = blockIdx.x, t = threadIdx.x;
    int lane = t & 31, warp = t >> 5;

    for (int e = t; e < 480; e += THREADS) sG[e] = d_G[e];
    if (t < 72) sRM[t] = d_rmask[t];

    // angles: x_w = tanh(v[b]·W[w] + b[w]) * pi ; fold layer-0 Rot
    const float* vrow = v + (size_t)b * 512;
    for (int w = warp; w < NQ; w += 8) {
        const float* Wr = W + w * 512;
        float acc = 0.f;
#pragma unroll
        for (int q = 0; q < 16; q++)
            acc = fmaf(vrow[lane + 32 * q], Wr[lane + 32 * q], acc);
#pragma unroll
        for (int o = 16; o; o >>= 1) acc += __shfl_xor_sync(0xFFFFFFFFu, acc, o);
        if (lane == 0) {
            float x = tanhf(acc + bc[w]) * PI_F;
            float ch = cosf(0.5f * x), sh = sinf(0.5f * x);
            float2 u00 = d_U0[w][0][0], u01 = d_U0[w][0][1];
            float2 u10 = d_U0[w][1][0], u11 = d_U0[w][1][1];
            sA[2 * w + 0] = make_float2(u00.x * ch + u01.x * sh, u00.y * ch + u01.y * sh);
            sA[2 * w + 1] = make_float2(u10.x * ch + u11.x * sh, u10.y * ch + u11.y * sh);
        }
    }
    __syncthreads();
    if (t < 16) {
        float2 h = sA[16 + (t & 1)];
        h = cmul(h, sA[18 + ((t >> 1) & 1)]);
        h = cmul(h, sA[20 + ((t >> 2) & 1)]);
        h = cmul(h, sA[22 + ((t >> 3) & 1)]);
        sH[t] = h;
    }
    __syncthreads();

    int tlo = t & 15, thi = t >> 4;
    int tc = t ^ (thi & 15);

    // Product-state init, written swizzled (amp j = t + 256*m at p(j) = (m<<8)|tc)
    {
        float2 tp = sA[t & 1];
#pragma unroll
        for (int w = 1; w < 8; w++)
            tp = cmul(tp, sA[2 * w + ((t >> w) & 1)]);
#pragma unroll
        for (int m = 0; m < 16; m++)
            S[(m << 8) | tc] = cmul(tp, sH[m]);
    }
    __syncthreads();

    float2 s[16];

#pragma unroll 1
    for (int l = 1; l <= 5; l++) {
        const u64* gl = sG + (l - 1) * 96;
        const unsigned* rm = sRM + (l - 1) * 12;

        // masked read into config A (fold CNOT ring of layer l-1)
        unsigned base = 0;
#pragma unroll
        for (int k = 0; k < 8; k++)
            base ^= rm[4 + k] & (unsigned)(-(int)((t >> k) & 1));
        unsigned r0 = rm[0], r1 = rm[1], r2 = rm[2], r3 = rm[3];
#pragma unroll
        for (int m = 0; m < 16; m++) {
            unsigned src = base;
            if (m & 1) src ^= r0;
            if (m & 2) src ^= r1;
            if (m & 4) src ^= r2;
            if (m & 8) src ^= r3;
            s[m] = S[src ^ ((src >> 4) & 15u)];
        }
        gates4(s, gl);          // qubits 0..3

        __syncthreads();
#pragma unroll
        for (int m = 0; m < 16; m++) S[(t << 4) | (m ^ tlo)] = s[m];   // write A
        __syncthreads();
#pragma unroll
        for (int m = 0; m < 16; m++) s[m] = S[(thi << 8) | (m << 4) | (tlo ^ m)]; // read B
        gates4(s, gl + 32);     // qubits 4..7

        __syncthreads();
#pragma unroll
        for (int m = 0; m < 16; m++) S[(thi << 8) | (m << 4) | (tlo ^ m)] = s[m]; // write B
        __syncthreads();
#pragma unroll
        for (int m = 0; m < 16; m++) s[m] = S[(m << 8) | tc];          // read C
        gates4(s, gl + 64);     // qubits 8..11

        if (l < 5) {
            __syncthreads();
#pragma unroll
            for (int m = 0; m < 16; m++) S[(m << 8) | tc] = s[m];      // write C
            __syncthreads();
        }
    }

    // Expvals from config-C registers; layer-5 CNOT ring folded via INVERSE masks.
    // sign bit w for amp i=(m<<8)|t is bit w of XOR_{k set in i} Rinv(e_k).
    {
        const unsigned* ri = sRM + 60;
        unsigned ptw = 0;
#pragma unroll
        for (int k = 0; k < 8; k++)
            ptw ^= ri[k] & (unsigned)(-(int)((t >> k) & 1));
        unsigned q8 = ri[8], q9 = ri[9], q10 = ri[10], q11 = ri[11];
        float z[12];
#pragma unroll
        for (int w = 0; w < 12; w++) z[w] = 0.f;
#pragma unroll
        for (int m = 0; m < 16; m++) {
            unsigned sw = ptw;
            if (m & 1) sw ^= q8;
            if (m & 2) sw ^= q9;
            if (m & 4) sw ^= q10;
            if (m & 8) sw ^= q11;
            float p = fmaf(s[m].x, s[m].x, s[m].y * s[m].y);
#pragma unroll
            for (int w = 0; w < 12; w++)
                z[w] += ((sw >> w) & 1) ? -p : p;
        }
#pragma unroll
        for (int w = 0; w < 12; w++) {
#pragma unroll
            for (int o = 16; o; o >>= 1)
                z[w] += __shfl_xor_sync(0xFFFFFFFFu, z[w], o);
        }
        __syncthreads();                 // state reads done; safe to reuse S
        float* red = (float*)S;
        if (lane == 0) {
#pragma unroll
            for (int w = 0; w < 12; w++) red[warp * 12 + w] = z[w];
        }
        __syncthreads();
        if (t < 12) {
            float sum = 0.f;
#pragma unroll
            for (int wp = 0; wp < 8; wp++) sum += red[wp * 12 + t];
            out[b * NQ + t] = sum;
        }
    }
}

// ---------------------------------------------------------------------------
extern "C" void kernel_launch(void* const* d_in, const int* in_sizes, int n_in,
                              void* d_out, int out_size) {
    const float* v = 0; const float* W = 0; const float* bc = 0; const float* wt = 0;
    for (int i = 0; i < n_in; i++) {
        if (in_sizes[i] == 4096 * 512)      v  = (const float*)d_in[i];
        else if (in_sizes[i] == 12 * 512)   W  = (const float*)d_in[i];
        else if (in_sizes[i] == 12)         bc = (const float*)d_in[i];
        else if (in_sizes[i] == 6 * 12 * 3) wt = (const float*)d_in[i];
    }
    float* out = (float*)d_out;

    precompute_kernel<<<1, 128>>>(wt);

    size_t shmem = 32768 + 3840 + 24 * 8 + 16 * 8 + 72 * 4;
    cudaFuncSetAttribute(qvl_kernel, cudaFuncAttributeMaxDynamicSharedMemorySize, (int)shmem);
    qvl_kernel<<<4096, THREADS, shmem>>>(v, W, bc, out);
}

// round 3
// speedup vs baseline: 1.3323x; 1.0848x over previous
#include <cuda_runtime.h>

#define NQ 12
#define THREADS 256
#define PI_F 3.14159265358979323846f
typedef unsigned long long u64;

// Staging (written by precompute kernel), then copied into __constant__
__device__ u64      g_G[630];
__device__ unsigned g_RM[72];
__device__ float2   g_U0[48];

__constant__ u64      cG[630];
__constant__ unsigned cRM[72];
__constant__ float2   cU0[48];

__device__ __forceinline__ float2 cmul(float2 a, float2 b) {
    return make_float2(a.x * b.x - a.y * b.y, a.x * b.y + a.y * b.x);
}
__device__ __forceinline__ u64 pk2(float a, float b) {
    u64 r; asm("mov.b64 %0,{%1,%2};" : "=l"(r) : "f"(a), "f"(b)); return r;
}
__device__ __forceinline__ void unpk(u64 x, float& a, float& b) {
    asm("mov.b64 {%0,%1},%2;" : "=f"(a), "=f"(b) : "l"(x));
}
__device__ __forceinline__ u64 m2(u64 a, u64 b) {
    u64 d; asm("mul.rn.f32x2 %0,%1,%2;" : "=l"(d) : "l"(a), "l"(b)); return d;
}
__device__ __forceinline__ u64 fma2(u64 a, u64 b, u64 c) {
    u64 d; asm("fma.rn.f32x2 %0,%1,%2,%3;" : "=l"(d) : "l"(a), "l"(b), "l"(c)); return d;
}
__device__ __forceinline__ u64 swp(u64 x) {
    float lo, hi; unpk(x, lo, hi); return pk2(hi, lo);
}

// ---------------------------------------------------------------------------
// Precompute kernel
// ---------------------------------------------------------------------------
__global__ void precompute_kernel(const float* __restrict__ weights) {
    __shared__ float2 U[6][NQ][2][2];
    int tid = threadIdx.x;

    for (int g = tid; g < 6 * NQ; g += blockDim.x) {
        float phi = weights[g * 3 + 0];
        float th  = weights[g * 3 + 1];
        float om  = weights[g * 3 + 2];
        float s = sinf(0.5f * th), c = cosf(0.5f * th);
        float ap = 0.5f * (phi + om), am = 0.5f * (phi - om);
        float sap = sinf(ap), cap = cosf(ap);
        float sam = sinf(am), cam = cosf(am);
        int l = g / NQ, w = g % NQ;
        U[l][w][0][0] = make_float2(cap * c, -sap * c);
        U[l][w][0][1] = make_float2(-cam * s, -sam * s);
        U[l][w][1][0] = make_float2(cam * s, -sam * s);
        U[l][w][1][1] = make_float2(cap * c, sap * c);
    }
    __syncthreads();

    // layer-0 matrices raw (folded into per-batch init)
    for (int e = tid; e < NQ * 4; e += blockDim.x) {
        int w = e >> 2;
        g_U0[e] = U[0][w][(e >> 1) & 1][e & 1];
    }
    // Packed coefficient blocks: per (layer 1..5, config 0..2): 42 u64
    //  3 broadcast gates (local bits 0..2): 12 u64 each: per entry {(re,re),(-im,-im),(im,im)}
    //  1 packing gate (local bit 3): 6 u64: P1,P2,P3,P4,Q3,Q4
    if (tid < 15) {
        int l = tid / 3 + 1, c = tid % 3;
        int base = (l - 1) * 126 + c * 42;
        for (int bit = 0; bit < 3; bit++) {
            for (int e = 0; e < 4; e++) {
                float2 u = U[l][c * 4 + bit][e >> 1][e & 1];
                int off = base + bit * 12 + e * 3;
                g_G[off + 0] = pk2(u.x, u.x);
                g_G[off + 1] = pk2(-u.y, -u.y);
                g_G[off + 2] = pk2(u.y, u.y);
            }
        }
        float2 u00 = U[l][c * 4 + 3][0][0], u01 = U[l][c * 4 + 3][0][1];
        float2 u10 = U[l][c * 4 + 3][1][0], u11 = U[l][c * 4 + 3][1][1];
        g_G[base + 36] = pk2(u00.x, u11.x);
        g_G[base + 37] = pk2(u01.x, u10.x);
        g_G[base + 38] = pk2(-u00.y, -u11.y);
        g_G[base + 39] = pk2(-u01.y, -u10.y);
        g_G[base + 40] = pk2(u00.y, u11.y);
        g_G[base + 41] = pk2(u01.y, u10.y);
    }
    // CNOT-ring masks: forward for layers 0..4 (read folding), inverse for layer 5.
    for (int e = tid; e < 6 * NQ; e += blockDim.x) {
        int l = e / NQ, bb = e % NQ;
        unsigned i = 1u << bb;
        if (l < 5) {
            int r = (l % (NQ - 1)) + 1;
            for (int w = NQ - 1; w >= 0; --w)
                i ^= ((i >> w) & 1u) << ((w + r) % NQ);
        } else {
            int r = (5 % (NQ - 1)) + 1;
            for (int w = 0; w < NQ; ++w)
                i ^= ((i >> w) & 1u) << ((w + r) % NQ);
        }
        g_RM[l * NQ + bb] = i;
    }
}

// ---------------------------------------------------------------------------
// Gates on SoA packed registers (RE[m],IM[m] pack amp pair (m, m+8))
// ---------------------------------------------------------------------------
template <int Q>
__device__ __forceinline__ void bgate(u64* RE, u64* IM, const u64* __restrict__ g) {
    u64 c00r = g[0], c00n = g[1], c00p = g[2];
    u64 c01r = g[3], c01n = g[4], c01p = g[5];
    u64 c10r = g[6], c10n = g[7], c10p = g[8];
    u64 c11r = g[9], c11n = g[10], c11p = g[11];
#pragma unroll
    for (int h = 0; h < 4; h++) {
        const int a = ((h >> Q) << (Q + 1)) | (h & ((1 << Q) - 1));
        const int bq = a + (1 << Q);
        u64 x0r = RE[a], x0i = IM[a], x1r = RE[bq], x1i = IM[bq];
        u64 y0r = m2(c00r, x0r); y0r = fma2(c00n, x0i, y0r); y0r = fma2(c01r, x1r, y0r); y0r = fma2(c01n, x1i, y0r);
        u64 y0i = m2(c00r, x0i); y0i = fma2(c00p, x0r, y0i); y0i = fma2(c01r, x1i, y0i); y0i = fma2(c01p, x1r, y0i);
        u64 y1r = m2(c10r, x0r); y1r = fma2(c10n, x0i, y1r); y1r = fma2(c11r, x1r, y1r); y1r = fma2(c11n, x1i, y1r);
        u64 y1i = m2(c10r, x0i); y1i = fma2(c10p, x0r, y1i); y1i = fma2(c11r, x1i, y1i); y1i = fma2(c11p, x1r, y1i);
        RE[a] = y0r; IM[a] = y0i; RE[bq] = y1r; IM[bq] = y1i;
    }
}

__device__ __forceinline__ void pgate(u64* RE, u64* IM, const u64* __restrict__ g) {
    u64 P1 = g[0], P2 = g[1], P3 = g[2], P4 = g[3], Q3 = g[4], Q4 = g[5];
#pragma unroll
    for (int m = 0; m < 8; m++) {
        u64 xr = RE[m], xi = IM[m];
        u64 sr = swp(xr), si = swp(xi);
        u64 yr = m2(P1, xr); yr = fma2(P2, sr, yr); yr = fma2(P3, xi, yr); yr = fma2(P4, si, yr);
        u64 yi = m2(P1, xi); yi = fma2(P2, si, yi); yi = fma2(Q3, xr, yi); yi = fma2(Q4, sr, yi);
        RE[m] = yr; IM[m] = yi;
    }
}

// ---------------------------------------------------------------------------
// Main kernel. SMEM SoA, swizzle phi(j) = j ^ ((j>>4)&31).
// Config A: j=(t<<4)|m  Config B: j=(thi<<8)|(m<<4)|tlo  Config C: j=(m<<8)|t
// ---------------------------------------------------------------------------
__global__ void __launch_bounds__(THREADS, 4) qvl_kernel(
    const float* __restrict__ v, const float* __restrict__ W,
    const float* __restrict__ bc, float* __restrict__ out) {
    __shared__ float Sre[4096];
    __shared__ float Sim[4096];
    __shared__ float2 sAH[40];   // [0..23]: per-qubit 2-vectors, [24..39]: high-bit product

    int b = blockIdx.x, t = threadIdx.x;
    int lane = t & 31, warp = t >> 5;

    // Angles: x_w = tanh(v[b]·W[w] + b[w]) * pi, fold layer-0 Rot
    const float* vrow = v + (size_t)b * 512;
    for (int w = warp; w < NQ; w += 8) {
        const float* Wr = W + w * 512;
        float acc = 0.f;
#pragma unroll
        for (int q = 0; q < 16; q++)
            acc = fmaf(vrow[lane + 32 * q], Wr[lane + 32 * q], acc);
#pragma unroll
        for (int o = 16; o; o >>= 1) acc += __shfl_xor_sync(0xFFFFFFFFu, acc, o);
        if (lane == 0) {
            float x = tanhf(acc + bc[w]) * PI_F;
            float ch = cosf(0.5f * x), sh = sinf(0.5f * x);
            float2 u00 = cU0[w * 4 + 0], u01 = cU0[w * 4 + 1];
            float2 u10 = cU0[w * 4 + 2], u11 = cU0[w * 4 + 3];
            sAH[2 * w + 0] = make_float2(u00.x * ch + u01.x * sh, u00.y * ch + u01.y * sh);
            sAH[2 * w + 1] = make_float2(u10.x * ch + u11.x * sh, u10.y * ch + u11.y * sh);
        }
    }
    __syncthreads();
    if (t < 16) {
        float2 h = sAH[16 + (t & 1)];
        h = cmul(h, sAH[18 + ((t >> 1) & 1)]);
        h = cmul(h, sAH[20 + ((t >> 2) & 1)]);
        h = cmul(h, sAH[22 + ((t >> 3) & 1)]);
        sAH[24 + t] = h;
    }
    __syncthreads();

    unsigned xC = (unsigned)t ^ (((unsigned)t >> 4) & 15u);
    unsigned xA = ((unsigned)t << 4) ^ ((unsigned)t & 31u);
    unsigned xB = ((((unsigned)t >> 4) << 8) | ((unsigned)t & 15u)) ^ ((((unsigned)t >> 4) & 1u) << 4);

    // Product-state init -> config C positions
    {
        float2 tp = sAH[t & 1];
#pragma unroll
        for (int w = 1; w < 8; w++)
            tp = cmul(tp, sAH[2 * w + ((t >> w) & 1)]);
#pragma unroll
        for (int m = 0; m < 16; m++) {
            float2 a = cmul(tp, sAH[24 + m]);
            unsigned ad = ((unsigned)m << 8) ^ xC ^ (((unsigned)m & 1u) << 4);
            Sre[ad] = a.x; Sim[ad] = a.y;
        }
    }
    __syncthreads();

    u64 RE[8], IM[8];

#pragma unroll 1
    for (int l = 1; l <= 5; l++) {
        const u64* gl = cG + (l - 1) * 126;
        const unsigned* rm = cRM + (l - 1) * 12;

        // ---- masked read into config A (fold CNOT ring of layer l-1) ----
        unsigned sb = 0;
#pragma unroll
        for (int k = 0; k < 8; k++)
            sb ^= rm[4 + k] & (unsigned)(-(int)((t >> k) & 1));
        unsigned r0 = rm[0], r1 = rm[1], r2 = rm[2], r3 = rm[3];
#pragma unroll
        for (int m = 0; m < 8; m++) {
            unsigned s0 = sb;
            if (m & 1) s0 ^= r0;
            if (m & 2) s0 ^= r1;
            if (m & 4) s0 ^= r2;
            unsigned s1 = s0 ^ r3;
            unsigned a0 = s0 ^ ((s0 >> 4) & 31u);
            unsigned a1 = s1 ^ ((s1 >> 4) & 31u);
            RE[m] = pk2(Sre[a0], Sre[a1]);
            IM[m] = pk2(Sim[a0], Sim[a1]);
        }
        bgate<0>(RE, IM, gl + 0);
        bgate<1>(RE, IM, gl + 12);
        bgate<2>(RE, IM, gl + 24);
        pgate(RE, IM, gl + 36);
        __syncthreads();
#pragma unroll
        for (int m = 0; m < 8; m++) {          // write A
            unsigned a0 = xA ^ (unsigned)m, a1 = a0 ^ 8u;
            float lo, hi;
            unpk(RE[m], lo, hi); Sre[a0] = lo; Sre[a1] = hi;
            unpk(IM[m], lo, hi); Sim[a0] = lo; Sim[a1] = hi;
        }
        __syncthreads();
#pragma unroll
        for (int m = 0; m < 8; m++) {          // read B
            unsigned a0 = xB ^ (unsigned)(m * 17), a1 = a0 ^ 136u;
            RE[m] = pk2(Sre[a0], Sre[a1]);
            IM[m] = pk2(Sim[a0], Sim[a1]);
        }
        bgate<0>(RE, IM, gl + 42);
        bgate<1>(RE, IM, gl + 54);
        bgate<2>(RE, IM, gl + 66);
        pgate(RE, IM, gl + 78);
#pragma unroll
        for (int m = 0; m < 8; m++) {          // write B (same per-thread set: no WAR sync)
            unsigned a0 = xB ^ (unsigned)(m * 17), a1 = a0 ^ 136u;
            float lo, hi;
            unpk(RE[m], lo, hi); Sre[a0] = lo; Sre[a1] = hi;
            unpk(IM[m], lo, hi); Sim[a0] = lo; Sim[a1] = hi;
        }
        __syncthreads();
#pragma unroll
        for (int m = 0; m < 8; m++) {          // read C
            unsigned a0 = xC ^ ((unsigned)m << 8) ^ (((unsigned)m & 1u) << 4);
            unsigned a1 = a0 ^ 2048u;
            RE[m] = pk2(Sre[a0], Sre[a1]);
            IM[m] = pk2(Sim[a0], Sim[a1]);
        }
        bgate<0>(RE, IM, gl + 84);
        bgate<1>(RE, IM, gl + 96);
        bgate<2>(RE, IM, gl + 108);
        pgate(RE, IM, gl + 120);
        if (l < 5) {
#pragma unroll
            for (int m = 0; m < 8; m++) {      // write C (same per-thread set)
                unsigned a0 = xC ^ ((unsigned)m << 8) ^ (((unsigned)m & 1u) << 4);
                unsigned a1 = a0 ^ 2048u;
                float lo, hi;
                unpk(RE[m], lo, hi); Sre[a0] = lo; Sre[a1] = hi;
                unpk(IM[m], lo, hi); Sim[a0] = lo; Sim[a1] = hi;
            }
            __syncthreads();
        }
    }

    // Expvals from config-C registers; layer-5 CNOT ring folded via inverse masks.
    {
        const unsigned* ri = cRM + 60;
        unsigned ptw = 0;
#pragma unroll
        for (int k = 0; k < 8; k++)
            ptw ^= ri[k] & (unsigned)(-(int)((t >> k) & 1));
        unsigned q8 = ri[8], q9 = ri[9], q10 = ri[10], q11 = ri[11];
        float p[16];
#pragma unroll
        for (int m = 0; m < 8; m++) {
            u64 P = m2(RE[m], RE[m]);
            P = fma2(IM[m], IM[m], P);
            unpk(P, p[m], p[m + 8]);
        }
        float z[12];
#pragma unroll
        for (int w = 0; w < 12; w++) z[w] = 0.f;
#pragma unroll
        for (int m = 0; m < 16; m++) {
            unsigned sw = ptw;
            if (m & 1) sw ^= q8;
            if (m & 2) sw ^= q9;
            if (m & 4) sw ^= q10;
            if (m & 8) sw ^= q11;
#pragma unroll
            for (int w = 0; w < 12; w++)
                z[w] += ((sw >> w) & 1) ? -p[m] : p[m];
        }
#pragma unroll
        for (int w = 0; w < 12; w++) {
#pragma unroll
            for (int o = 16; o; o >>= 1)
                z[w] += __shfl_xor_sync(0xFFFFFFFFu, z[w], o);
        }
        __syncthreads();                 // all SMEM reads done; reuse Sre as scratch
        if (lane == 0) {
#pragma unroll
            for (int w = 0; w < 12; w++) Sre[warp * 12 + w] = z[w];
        }
        __syncthreads();
        if (t < 12) {
            float sum = 0.f;
#pragma unroll
            for (int wp = 0; wp < 8; wp++) sum += Sre[wp * 12 + t];
            out[b * NQ + t] = sum;
        }
    }
}

// ---------------------------------------------------------------------------
extern "C" void kernel_launch(void* const* d_in, const int* in_sizes, int n_in,
                              void* d_out, int out_size) {
    const float* v = 0; const float* W = 0; const float* bc = 0; const float* wt = 0;
    for (int i = 0; i < n_in; i++) {
        if (in_sizes[i] == 4096 * 512)      v  = (const float*)d_in[i];
        else if (in_sizes[i] == 12 * 512)   W  = (const float*)d_in[i];
        else if (in_sizes[i] == 12)         bc = (const float*)d_in[i];
        else if (in_sizes[i] == 6 * 12 * 3) wt = (const float*)d_in[i];
    }
    float* out = (float*)d_out;

    precompute_kernel<<<1, 128>>>(wt);

    void *pG = 0, *pRM = 0, *pU0 = 0;
    cudaGetSymbolAddress(&pG, g_G);
    cudaGetSymbolAddress(&pRM, g_RM);
    cudaGetSymbolAddress(&pU0, g_U0);
    cudaMemcpyToSymbolAsync(cG,  pG,  sizeof(g_G),  0, cudaMemcpyDeviceToDevice, 0);
    cudaMemcpyToSymbolAsync(cRM, pRM, sizeof(g_RM), 0, cudaMemcpyDeviceToDevice, 0);
    cudaMemcpyToSymbolAsync(cU0, pU0, sizeof(g_U0), 0, cudaMemcpyDeviceToDevice, 0);

    qvl_kernel<<<4096, THREADS>>>(v, W, bc, out);
}